// round 11
// baseline (speedup 1.0000x reference)
#include <cuda_runtime.h>
#include <cuda_fp16.h>
#include <mma.h>
#include <cstdint>

using namespace nvcuda;

#define Ecfg 1024
#define Hh   16
#define HKV  4
#define Dd   64

#define BM  128
#define BN  128
#define BKg 64
#define LDA 72    // halves (64 + 8 pad)
#define LDK 72    // halves

// ---------------- scratch (device globals) ----------------
__device__ float  g_qraw[2 * 2048 * 1024];
__device__ float  g_kraw[2 * 2048 * 256];
__device__ float  g_vraw[2 * 2048 * 256];
__device__ __half g_qt [2 * 16 * 2048 * 64];
__device__ __half g_kt [2 * 4  * 2048 * 64];
__device__ __half g_vt [2 * 4  * 2048 * 64];
__device__ __half g_y  [2 * 2048 * 1024];
__device__ __half g_xh [2 * 2048 * 1024];
__device__ __half g_wqh[1024 * 1024];
__device__ __half g_wkh[256 * 1024];
__device__ __half g_wvh[256 * 1024];
__device__ __half g_wph[1024 * 1024];

// ---------------- cp.async helpers ----------------
__device__ __forceinline__ void cp16(void* smem_dst, const void* gsrc) {
    uint32_t s = (uint32_t)__cvta_generic_to_shared(smem_dst);
    asm volatile("cp.async.cg.shared.global [%0], [%1], 16;\n" :: "r"(s), "l"(gsrc));
}
#define CP_COMMIT() asm volatile("cp.async.commit_group;\n" ::: "memory")
#define CP_WAIT1()  asm volatile("cp.async.wait_group 1;\n" ::: "memory")
#define CP_WAIT0()  asm volatile("cp.async.wait_group 0;\n" ::: "memory")

__device__ __forceinline__ uint32_t smem_u32(const void* p) {
    return (uint32_t)__cvta_generic_to_shared(p);
}

// ---------------- mma / ldmatrix primitives ----------------
__device__ __forceinline__ void mma16816(float d[4], const uint32_t a[4],
                                         uint32_t b0, uint32_t b1) {
    asm volatile(
        "mma.sync.aligned.m16n8k16.row.col.f32.f16.f16.f32 "
        "{%0,%1,%2,%3}, {%4,%5,%6,%7}, {%8,%9}, {%0,%1,%2,%3};"
        : "+f"(d[0]), "+f"(d[1]), "+f"(d[2]), "+f"(d[3])
        : "r"(a[0]), "r"(a[1]), "r"(a[2]), "r"(a[3]), "r"(b0), "r"(b1));
}
__device__ __forceinline__ void ldm4(uint32_t r[4], uint32_t addr) {
    asm volatile("ldmatrix.sync.aligned.m8n8.x4.shared.b16 {%0,%1,%2,%3}, [%4];"
                 : "=r"(r[0]), "=r"(r[1]), "=r"(r[2]), "=r"(r[3]) : "r"(addr));
}
__device__ __forceinline__ void ldm4t(uint32_t r[4], uint32_t addr) {
    asm volatile("ldmatrix.sync.aligned.m8n8.x4.trans.shared.b16 {%0,%1,%2,%3}, [%4];"
                 : "=r"(r[0]), "=r"(r[1]), "=r"(r[2]), "=r"(r[3]) : "r"(addr));
}

// ---------------- fast exp2 (no MUFU) ----------------
__device__ __forceinline__ float fast_exp2(float x) {
    float t = x + 12582912.0f;
    int   ei = __float_as_int(t) - 0x4B400000;
    float f = x - (t - 12582912.0f);
    float e = fmaf(f, 0.0013333558f, 0.0096181291f);
    e = fmaf(f, e, 0.0555041087f);
    e = fmaf(f, e, 0.2402265070f);
    e = fmaf(f, e, 0.6931471806f);
    e = fmaf(f, e, 1.0f);
    return __int_as_float(__float_as_int(e) + (ei << 23));
}
#define LOG2E_F  1.4426950408889634f
#define NBIAS_F  (-11.541560327111707f)

// ---------------- fused fp16 convert of x + all weights (1 launch) ----------------
#define N4_WQ 262144
#define N4_WK 65536
#define N4_WV 65536
#define N4_WP 262144
__global__ void cvt_all(const float* __restrict__ x,  const float* __restrict__ wq,
                        const float* __restrict__ wk, const float* __restrict__ wv,
                        const float* __restrict__ wp,
                        __half* __restrict__ xo, __half* __restrict__ wqo,
                        __half* __restrict__ wko, __half* __restrict__ wvo,
                        __half* __restrict__ wpo, int n4x) {
    int i = blockIdx.x * blockDim.x + threadIdx.x;
    const float4* s; __half* d; int j;
    if (i < n4x) { s = (const float4*)x; d = xo; j = i; }
    else {
        i -= n4x;
        if (i < N4_WQ)                          { s = (const float4*)wq; d = wqo; j = i; }
        else if (i < N4_WQ + N4_WK)             { s = (const float4*)wk; d = wko; j = i - N4_WQ; }
        else if (i < N4_WQ + N4_WK + N4_WV)     { s = (const float4*)wv; d = wvo; j = i - N4_WQ - N4_WK; }
        else if (i < N4_WQ + N4_WK + N4_WV + N4_WP) { s = (const float4*)wp; d = wpo; j = i - N4_WQ - N4_WK - N4_WV; }
        else return;
    }
    float4 v = s[j];
    __half2 h0 = __floats2half2_rn(v.x, v.y);
    __half2 h1 = __floats2half2_rn(v.z, v.w);
    *reinterpret_cast<__half2*>(&d[j * 4])     = h0;
    *reinterpret_cast<__half2*>(&d[j * 4 + 2]) = h1;
}

// ================= FP16 GEMM, cp.async 2-stage, BK=64 =================
// BM=BN=128, 256 thr = 8 warps (2M x 4N), warp tile 64x32. 16 K-slabs -> 16 sync pairs.
__device__ __forceinline__ void gemm_core(
    const __half* __restrict__ A, const __half* __restrict__ W,
    float* __restrict__ C, int N, int K, int m0, int n0) {
    extern __shared__ __half smh[];
    __half* As = smh;                      // 2 * 128 * LDA
    __half* Ws = smh + 2 * BM * LDA;       // 2 * 128 * LDA
    const int tid = threadIdx.x;
    const int warp = tid >> 5;
    const int wm = warp >> 2;
    const int wn = warp & 3;

    wmma::fragment<wmma::accumulator, 16, 16, 16, float> acc[4][2];
#pragma unroll
    for (int i = 0; i < 4; i++)
#pragma unroll
        for (int j = 0; j < 2; j++) wmma::fill_fragment(acc[i][j], 0.f);

    const __half* Ab = A + (size_t)m0 * K;
    const __half* Wb = W + (size_t)n0 * K;

#define LOAD_SLAB(it, buf)                                                      \
    {                                                                           \
        const int k0 = (it) << 6;                                               \
        __half* ad = As + (buf) * BM * LDA;                                     \
        __half* wd = Ws + (buf) * BN * LDA;                                     \
        _Pragma("unroll")                                                       \
        for (int i = 0; i < 4; i++) {                                           \
            int ch = tid + i * 256;          /* 0..1023 */                      \
            int r = ch >> 3, c8 = (ch & 7) << 3;                                \
            cp16(ad + r * LDA + c8, Ab + (size_t)r * K + k0 + c8);              \
            cp16(wd + r * LDA + c8, Wb + (size_t)r * K + k0 + c8);              \
        }                                                                       \
    }

    const int nIter = K >> 6;
    LOAD_SLAB(0, 0); CP_COMMIT();
    for (int it = 0; it < nIter; ++it) {
        const int buf = it & 1;
        if (it + 1 < nIter) { LOAD_SLAB(it + 1, buf ^ 1); CP_COMMIT(); CP_WAIT1(); }
        else CP_WAIT0();
        __syncthreads();
        const __half* as = As + buf * BM * LDA;
        const __half* ws = Ws + buf * BN * LDA;
#pragma unroll
        for (int kk = 0; kk < BKg; kk += 16) {
            wmma::fragment<wmma::matrix_a, 16, 16, 16, __half, wmma::row_major> a[4];
            wmma::fragment<wmma::matrix_b, 16, 16, 16, __half, wmma::col_major> b[2];
#pragma unroll
            for (int i = 0; i < 4; i++)
                wmma::load_matrix_sync(a[i], &as[(wm * 64 + i * 16) * LDA + kk], LDA);
#pragma unroll
            for (int j = 0; j < 2; j++)
                wmma::load_matrix_sync(b[j], &ws[(wn * 32 + j * 16) * LDA + kk], LDA);
#pragma unroll
            for (int i = 0; i < 4; i++)
#pragma unroll
                for (int j = 0; j < 2; j++)
                    wmma::mma_sync(acc[i][j], a[i], b[j], acc[i][j]);
        }
        __syncthreads();
    }
#undef LOAD_SLAB
#pragma unroll
    for (int i = 0; i < 4; i++)
#pragma unroll
        for (int j = 0; j < 2; j++)
            wmma::store_matrix_sync(&C[(size_t)(m0 + wm * 64 + i * 16) * N + n0 + wn * 32 + j * 16],
                                    acc[i][j], N, wmma::mem_row_major);
}

__global__ __launch_bounds__(256) void gemm_proj(
    const __half* __restrict__ A, const __half* __restrict__ W, float* __restrict__ C, int K) {
    gemm_core(A, W, C, Ecfg, K, blockIdx.y * BM, blockIdx.x * BN);
}

__global__ __launch_bounds__(256) void gemm_qkv(
    const __half* __restrict__ x,
    const __half* __restrict__ Wq, const __half* __restrict__ Wk, const __half* __restrict__ Wv,
    float* __restrict__ Cq, float* __restrict__ Ck, float* __restrict__ Cv, int K) {
    const int ng = blockIdx.x * BN;
    const __half* W; float* C; int N, n0;
    if (ng < 1024)      { W = Wq; C = Cq; N = 1024; n0 = ng; }
    else if (ng < 1280) { W = Wk; C = Ck; N = 256;  n0 = ng - 1024; }
    else                { W = Wv; C = Cv; N = 256;  n0 = ng - 1280; }
    gemm_core(x, W, C, N, K, blockIdx.y * BM, n0);
}

// ---------------- rope + rmsnorm for Q (fp16, pre-scaled 1/8) ----------------
__global__ void rope_rms_kernel(const float* __restrict__ raw,
                                const float* __restrict__ cosb,
                                const float* __restrict__ sinb,
                                __half* __restrict__ dst, int T) {
    const int warp = threadIdx.x >> 5, lane = threadIdx.x & 31;
    const int t = blockIdx.x * 8 + warp;
    const int h = blockIdx.y, b = blockIdx.z;
    const int NH = gridDim.y;
    const float* src = raw + (((size_t)b * T + t) * NH + h) * 64;
    float x1 = src[lane], x2 = src[32 + lane];
    float c = cosb[(size_t)t * 32 + lane];
    float s = sinb[(size_t)t * 32 + lane];
    float r1 = x1 * c + x2 * s;
    float r2 = x2 * c - x1 * s;
    float ss = r1 * r1 + r2 * r2;
#pragma unroll
    for (int o = 16; o; o >>= 1) ss += __shfl_xor_sync(0xffffffffu, ss, o);
    float inv = rsqrtf(ss * (1.f / 64.f) + 1.1920929e-07f) * 0.125f;
    __half* d = dst + (((size_t)b * NH + h) * T + t) * 64;
    d[lane] = __float2half(r1 * inv);
    d[32 + lane] = __float2half(r2 * inv);
}

// ---------------- fused K rope+rms AND V gate (fp16) ----------------
__global__ void kv_post_kernel(const float* __restrict__ kraw,
                               const float* __restrict__ vraw,
                               const float* __restrict__ x,
                               const float* __restrict__ ve,
                               const float* __restrict__ cosb,
                               const float* __restrict__ sinb,
                               const float* __restrict__ Wgate,
                               __half* __restrict__ k_t,
                               __half* __restrict__ v_t, int T) {
    const int warp = threadIdx.x >> 5, lane = threadIdx.x & 31;
    const int t = blockIdx.x * 8 + warp;
    const int h = blockIdx.y, b = blockIdx.z;
    const size_t tok = (size_t)b * T + t;
    {
        const float* src = kraw + (tok * HKV + h) * 64;
        float x1 = src[lane], x2 = src[32 + lane];
        float c = cosb[(size_t)t * 32 + lane];
        float s = sinb[(size_t)t * 32 + lane];
        float r1 = x1 * c + x2 * s;
        float r2 = x2 * c - x1 * s;
        float ss = r1 * r1 + r2 * r2;
#pragma unroll
        for (int o = 16; o; o >>= 1) ss += __shfl_xor_sync(0xffffffffu, ss, o);
        float inv = rsqrtf(ss * (1.f / 64.f) + 1.1920929e-07f);
        __half* d = k_t + (((size_t)b * HKV + h) * T + t) * 64;
        d[lane] = __float2half(r1 * inv);
        d[32 + lane] = __float2half(r2 * inv);
    }
    {
        float g = x[tok * Ecfg + lane] * Wgate[h * 32 + lane];
#pragma unroll
        for (int o = 16; o; o >>= 1) g += __shfl_xor_sync(0xffffffffu, g, o);
        float gate = 2.f / (1.f + __expf(-g));
        const float* vs = vraw + (tok * HKV + h) * 64;
        const float* ves = ve + (tok * HKV + h) * 64;
        __half* d = v_t + (((size_t)b * HKV + h) * T + t) * 64;
        d[lane] = __float2half(vs[lane] + gate * ves[lane]);
        d[32 + lane] = __float2half(vs[32 + lane] + gate * ves[32 + lane]);
    }
}

// ================ flash attention: GQA-paired, raw mma + register softmax ================
// 256 thr = 8 warps; warps 0-3 -> head A, warps 4-7 -> head B (same KV head),
// sharing one double-buffered K/V pipeline. Each warp owns 32 query rows.
__global__ __launch_bounds__(256) void attn_mma(
    const __half* __restrict__ q, const __half* __restrict__ k,
    const __half* __restrict__ v, __half* __restrict__ out,
    const int* __restrict__ wptr, int T) {
    extern __shared__ __half smh[];
    __half* Ks = smh;                  // 2 * 64 * LDK
    __half* Vs = smh + 2 * 64 * LDK;   // 2 * 64 * LDK
    const uint32_t ks0 = smem_u32(Ks);
    const uint32_t vs0 = smem_u32(Vs);

    const int qtile = blockIdx.x, pair = blockIdx.y, b = blockIdx.z;
    const int hkv = pair >> 1;
    const int W = wptr[0];
    const int tid = threadIdx.x;
    const int warp = tid >> 5, lane = tid & 31;
    const int wh = warp >> 2;                  // head within pair
    const int wrow = warp & 3;                 // 32-row strip index
    const int h = hkv * 4 + (pair & 1) * 2 + wh;
    const int qbase = qtile * 128;
    const int rq = lane >> 2;
    const int qc = (lane & 3) << 1;

    const int krow = ((lane >> 4) << 3) + (lane & 7);
    const int kcol = ((lane >> 3) & 1) << 3;
    const int vrow = (((lane >> 3) & 1) << 3) + (lane & 7);
    const int vcol = (lane >> 4) << 3;

    // ---- persistent Q A-fragments from gmem ----
    uint32_t qa[2][4][4];
#pragma unroll
    for (int i = 0; i < 2; i++) {
        const __half* q0 = q + ((size_t)(b * Hh + h) * T + qbase + wrow * 32 + i * 16 + rq) * Dd;
        const __half* q8 = q0 + 8 * Dd;
#pragma unroll
        for (int t = 0; t < 4; t++) {
            qa[i][t][0] = *reinterpret_cast<const uint32_t*>(q0 + t * 16 + qc);
            qa[i][t][1] = *reinterpret_cast<const uint32_t*>(q8 + t * 16 + qc);
            qa[i][t][2] = *reinterpret_cast<const uint32_t*>(q0 + t * 16 + 8 + qc);
            qa[i][t][3] = *reinterpret_cast<const uint32_t*>(q8 + t * 16 + 8 + qc);
        }
    }

    float o[2][8][4];
#pragma unroll
    for (int i = 0; i < 2; i++)
#pragma unroll
        for (int j = 0; j < 8; j++)
#pragma unroll
            for (int c = 0; c < 4; c++) o[i][j][c] = 0.f;
    float lsum[2][2] = {{0.f, 0.f}, {0.f, 0.f}};

    const __half* kb = k + (size_t)(b * HKV + hkv) * T * Dd;
    const __half* vb = v + (size_t)(b * HKV + hkv) * T * Dd;
    int kmin = qbase - W; if (kmin < 0) kmin = 0;
    const int t0 = kmin >> 6;
    const int ktend = 2 * qtile + 1;

#define LOAD_KV(kt, buf)                                                        \
    {                                                                           \
        const __half* kp = kb + (size_t)(kt) * 64 * Dd;                         \
        const __half* vp = vb + (size_t)(kt) * 64 * Dd;                         \
        __half* kd = Ks + (buf) * 64 * LDK;                                     \
        __half* vd = Vs + (buf) * 64 * LDK;                                     \
        _Pragma("unroll")                                                       \
        for (int i = 0; i < 2; i++) {                                           \
            int ch = tid + i * 256;           /* 0..511 */                      \
            int r = ch >> 3, c8 = (ch & 7) << 3;                                \
            cp16(kd + r * LDK + c8, kp + r * 64 + c8);                          \
            cp16(vd + r * LDK + c8, vp + r * 64 + c8);                          \
        }                                                                       \
    }

    LOAD_KV(t0, 0); CP_COMMIT();

    for (int kt = t0; kt <= ktend; ++kt) {
        const int buf = (kt - t0) & 1;
        if (kt < ktend) { LOAD_KV(kt + 1, buf ^ 1); CP_COMMIT(); CP_WAIT1(); }
        else CP_WAIT0();
        __syncthreads();
        const uint32_t ksb = ks0 + buf * 64 * LDK * 2;
        const uint32_t vsb = vs0 + buf * 64 * LDK * 2;

#pragma unroll
        for (int t = 0; t < 4; t++) {
            float s[2][2][4];
#pragma unroll
            for (int i = 0; i < 2; i++)
#pragma unroll
                for (int jj = 0; jj < 2; jj++)
#pragma unroll
                    for (int c = 0; c < 4; c++) s[i][jj][c] = 0.f;
#pragma unroll
            for (int kd = 0; kd < 4; kd++) {
                uint32_t kbf[4];
                ldm4(kbf, ksb + (uint32_t)(((t * 16 + krow) * LDK + kd * 16 + kcol) * 2));
                mma16816(s[0][0], qa[0][kd], kbf[0], kbf[1]);
                mma16816(s[0][1], qa[0][kd], kbf[2], kbf[3]);
                mma16816(s[1][0], qa[1][kd], kbf[0], kbf[1]);
                mma16816(s[1][1], qa[1][kd], kbf[2], kbf[3]);
            }
            uint32_t pa[2][4];
#pragma unroll
            for (int i = 0; i < 2; i++) {
                const int row0 = qbase + wrow * 32 + i * 16 + rq;
#pragma unroll
                for (int jj = 0; jj < 2; jj++) {
                    const int colb = (kt << 6) + t * 16 + jj * 8 + qc;
#pragma unroll
                    for (int c = 0; c < 4; c++) {
                        const int row = row0 + ((c >> 1) << 3);
                        const int col = colb + (c & 1);
                        float pv = 0.f;
                        if (col <= row && col >= row - W) {
                            pv = fast_exp2(fmaf(s[i][jj][c], LOG2E_F, NBIAS_F));
                            lsum[i][c >> 1] += pv;
                        }
                        s[i][jj][c] = pv;
                    }
                    __half2 lo = __floats2half2_rn(s[i][jj][0], s[i][jj][1]);
                    __half2 hi = __floats2half2_rn(s[i][jj][2], s[i][jj][3]);
                    pa[i][jj * 2 + 0] = *reinterpret_cast<uint32_t*>(&lo);
                    pa[i][jj * 2 + 1] = *reinterpret_cast<uint32_t*>(&hi);
                }
            }
#pragma unroll
            for (int jdp = 0; jdp < 4; jdp++) {
                uint32_t vbf[4];
                ldm4t(vbf, vsb + (uint32_t)(((t * 16 + vrow) * LDK + jdp * 16 + vcol) * 2));
                mma16816(o[0][jdp * 2 + 0], pa[0], vbf[0], vbf[1]);
                mma16816(o[0][jdp * 2 + 1], pa[0], vbf[2], vbf[3]);
                mma16816(o[1][jdp * 2 + 0], pa[1], vbf[0], vbf[1]);
                mma16816(o[1][jdp * 2 + 1], pa[1], vbf[2], vbf[3]);
            }
        }
        __syncthreads();
    }
#undef LOAD_KV

    // ---- epilogue: quad-reduce l, normalize, write fp16 y [B,T,H,D] ----
#pragma unroll
    for (int i = 0; i < 2; i++) {
#pragma unroll
        for (int rh = 0; rh < 2; rh++) {
            float l = lsum[i][rh];
            l += __shfl_xor_sync(0xffffffffu, l, 1);
            l += __shfl_xor_sync(0xffffffffu, l, 2);
            const float inv = 1.f / l;
            const int qrow = qbase + wrow * 32 + i * 16 + rq + rh * 8;
            __half* op = out + ((size_t)(b * T + qrow) * Hh + h) * Dd + qc;
#pragma unroll
            for (int jd = 0; jd < 8; jd++) {
                __half2 hv = __floats2half2_rn(o[i][jd][rh * 2] * inv,
                                               o[i][jd][rh * 2 + 1] * inv);
                *reinterpret_cast<__half2*>(op + jd * 8) = hv;
            }
        }
    }
}

// ---------------- launch ----------------
extern "C" void kernel_launch(void* const* d_in, const int* in_sizes, int n_in,
                              void* d_out, int out_size) {
    const float* x     = (const float*)d_in[0];
    const float* ve    = (const float*)d_in[1];
    const float* cosb  = (const float*)d_in[2];
    const float* sinb  = (const float*)d_in[3];
    const float* Wq    = (const float*)d_in[4];
    const float* Wk    = (const float*)d_in[5];
    const float* Wv    = (const float*)d_in[6];
    const float* Wproj = (const float*)d_in[7];
    const float* Wgate = (const float*)d_in[8];
    const int*   wsz   = (const int*)d_in[9];

    int T = in_sizes[2] / 32;
    int B = in_sizes[0] / (T * Ecfg);
    int M = B * T;

    float *qraw, *kraw, *vraw;
    __half *qt, *kt, *vt, *y, *xh, *wqh, *wkh, *wvh, *wph;
    cudaGetSymbolAddress((void**)&qraw, g_qraw);
    cudaGetSymbolAddress((void**)&kraw, g_kraw);
    cudaGetSymbolAddress((void**)&vraw, g_vraw);
    cudaGetSymbolAddress((void**)&qt,   g_qt);
    cudaGetSymbolAddress((void**)&kt,   g_kt);
    cudaGetSymbolAddress((void**)&vt,   g_vt);
    cudaGetSymbolAddress((void**)&y,    g_y);
    cudaGetSymbolAddress((void**)&xh,   g_xh);
    cudaGetSymbolAddress((void**)&wqh,  g_wqh);
    cudaGetSymbolAddress((void**)&wkh,  g_wkh);
    cudaGetSymbolAddress((void**)&wvh,  g_wvh);
    cudaGetSymbolAddress((void**)&wph,  g_wph);

    const int gemm_smem = 2 * (BM + BN) * LDA * 2;   // 73728
    const int attn_smem = 4 * 64 * LDK * 2;          // 36864
    cudaFuncSetAttribute(gemm_qkv,  cudaFuncAttributeMaxDynamicSharedMemorySize, gemm_smem);
    cudaFuncSetAttribute(gemm_proj, cudaFuncAttributeMaxDynamicSharedMemorySize, gemm_smem);
    cudaFuncSetAttribute(attn_mma,  cudaFuncAttributeMaxDynamicSharedMemorySize, attn_smem);

    {
        int n4x = M * Ecfg / 4;
        int total = n4x + N4_WQ + N4_WK + N4_WV + N4_WP;
        cvt_all<<<(total + 255) / 256, 256>>>(x, Wq, Wk, Wv, Wproj,
                                              xh, wqh, wkh, wvh, wph, n4x);
    }

    gemm_qkv<<<dim3(1536 / BN, M / BM), 256, gemm_smem>>>(xh, wqh, wkh, wvh, qraw, kraw, vraw, Ecfg);

    rope_rms_kernel<<<dim3(T / 8, Hh, B), 256>>>(qraw, cosb, sinb, qt, T);
    kv_post_kernel <<<dim3(T / 8, HKV, B), 256>>>(kraw, vraw, x, ve, cosb, sinb, Wgate, kt, vt, T);

    attn_mma<<<dim3(T / 128, HKV * 2, B), 256, attn_smem>>>(qt, kt, vt, y, wsz, T);

    gemm_proj<<<dim3(Ecfg / BN, M / BM), 256, gemm_smem>>>(y, wph, (float*)d_out, Ecfg);
}

// round 12
// speedup vs baseline: 1.2431x; 1.2431x over previous
#include <cuda_runtime.h>
#include <cuda_fp16.h>
#include <mma.h>
#include <cstdint>

using namespace nvcuda;

#define Ecfg 1024
#define Hh   16
#define HKV  4
#define Dd   64

#define BM  128
#define BN  128
#define BKg 64
#define LDA 72    // halves (64 + 8 pad)
#define LDK 72    // halves

// ---------------- scratch (device globals) ----------------
__device__ float  g_qraw[2 * 2048 * 1024];
__device__ float  g_kraw[2 * 2048 * 256];
__device__ float  g_vraw[2 * 2048 * 256];
__device__ __half g_qt [2 * 16 * 2048 * 64];
__device__ __half g_kt [2 * 4  * 2048 * 64];
__device__ __half g_vt [2 * 4  * 2048 * 64];
__device__ __half g_y  [2 * 2048 * 1024];
__device__ __half g_xh [2 * 2048 * 1024];
__device__ __half g_wqh[1024 * 1024];
__device__ __half g_wkh[256 * 1024];
__device__ __half g_wvh[256 * 1024];
__device__ __half g_wph[1024 * 1024];

// ---------------- cp.async helpers ----------------
__device__ __forceinline__ void cp16(void* smem_dst, const void* gsrc) {
    uint32_t s = (uint32_t)__cvta_generic_to_shared(smem_dst);
    asm volatile("cp.async.cg.shared.global [%0], [%1], 16;\n" :: "r"(s), "l"(gsrc));
}
#define CP_COMMIT() asm volatile("cp.async.commit_group;\n" ::: "memory")
#define CP_WAIT1()  asm volatile("cp.async.wait_group 1;\n" ::: "memory")
#define CP_WAIT0()  asm volatile("cp.async.wait_group 0;\n" ::: "memory")

__device__ __forceinline__ uint32_t smem_u32(const void* p) {
    return (uint32_t)__cvta_generic_to_shared(p);
}

// ---------------- mma / ldmatrix primitives ----------------
__device__ __forceinline__ void mma16816(float d[4], const uint32_t a[4],
                                         uint32_t b0, uint32_t b1) {
    asm volatile(
        "mma.sync.aligned.m16n8k16.row.col.f32.f16.f16.f32 "
        "{%0,%1,%2,%3}, {%4,%5,%6,%7}, {%8,%9}, {%0,%1,%2,%3};"
        : "+f"(d[0]), "+f"(d[1]), "+f"(d[2]), "+f"(d[3])
        : "r"(a[0]), "r"(a[1]), "r"(a[2]), "r"(a[3]), "r"(b0), "r"(b1));
}
__device__ __forceinline__ void ldm4(uint32_t r[4], uint32_t addr) {
    asm volatile("ldmatrix.sync.aligned.m8n8.x4.shared.b16 {%0,%1,%2,%3}, [%4];"
                 : "=r"(r[0]), "=r"(r[1]), "=r"(r[2]), "=r"(r[3]) : "r"(addr));
}
__device__ __forceinline__ void ldm4t(uint32_t r[4], uint32_t addr) {
    asm volatile("ldmatrix.sync.aligned.m8n8.x4.trans.shared.b16 {%0,%1,%2,%3}, [%4];"
                 : "=r"(r[0]), "=r"(r[1]), "=r"(r[2]), "=r"(r[3]) : "r"(addr));
}

// ---------------- fast exp2 (no MUFU) ----------------
__device__ __forceinline__ float fast_exp2(float x) {
    float t = x + 12582912.0f;
    int   ei = __float_as_int(t) - 0x4B400000;
    float f = x - (t - 12582912.0f);
    float e = fmaf(f, 0.0013333558f, 0.0096181291f);
    e = fmaf(f, e, 0.0555041087f);
    e = fmaf(f, e, 0.2402265070f);
    e = fmaf(f, e, 0.6931471806f);
    e = fmaf(f, e, 1.0f);
    return __int_as_float(__float_as_int(e) + (ei << 23));
}
#define LOG2E_F  1.4426950408889634f
#define NBIAS_F  (-11.541560327111707f)

// ---------------- fused fp16 convert of x + all weights (1 launch) ----------------
#define N4_WQ 262144
#define N4_WK 65536
#define N4_WV 65536
#define N4_WP 262144
__global__ void cvt_all(const float* __restrict__ x,  const float* __restrict__ wq,
                        const float* __restrict__ wk, const float* __restrict__ wv,
                        const float* __restrict__ wp,
                        __half* __restrict__ xo, __half* __restrict__ wqo,
                        __half* __restrict__ wko, __half* __restrict__ wvo,
                        __half* __restrict__ wpo, int n4x) {
    int i = blockIdx.x * blockDim.x + threadIdx.x;
    const float4* s; __half* d; int j;
    if (i < n4x) { s = (const float4*)x; d = xo; j = i; }
    else {
        i -= n4x;
        if (i < N4_WQ)                          { s = (const float4*)wq; d = wqo; j = i; }
        else if (i < N4_WQ + N4_WK)             { s = (const float4*)wk; d = wko; j = i - N4_WQ; }
        else if (i < N4_WQ + N4_WK + N4_WV)     { s = (const float4*)wv; d = wvo; j = i - N4_WQ - N4_WK; }
        else if (i < N4_WQ + N4_WK + N4_WV + N4_WP) { s = (const float4*)wp; d = wpo; j = i - N4_WQ - N4_WK - N4_WV; }
        else return;
    }
    float4 v = s[j];
    __half2 h0 = __floats2half2_rn(v.x, v.y);
    __half2 h1 = __floats2half2_rn(v.z, v.w);
    *reinterpret_cast<__half2*>(&d[j * 4])     = h0;
    *reinterpret_cast<__half2*>(&d[j * 4 + 2]) = h1;
}

// ================= FP16 GEMM, cp.async 2-stage, BK=64 =================
// BM=BN=128, 256 thr = 8 warps (2M x 4N), warp tile 64x32. 16 K-slabs.
__device__ __forceinline__ void gemm_core(
    const __half* __restrict__ A, const __half* __restrict__ W,
    float* __restrict__ C, int N, int K, int m0, int n0) {
    extern __shared__ __half smh[];
    __half* As = smh;                      // 2 * 128 * LDA
    __half* Ws = smh + 2 * BM * LDA;       // 2 * 128 * LDA
    const int tid = threadIdx.x;
    const int warp = tid >> 5;
    const int wm = warp >> 2;
    const int wn = warp & 3;

    wmma::fragment<wmma::accumulator, 16, 16, 16, float> acc[4][2];
#pragma unroll
    for (int i = 0; i < 4; i++)
#pragma unroll
        for (int j = 0; j < 2; j++) wmma::fill_fragment(acc[i][j], 0.f);

    const __half* Ab = A + (size_t)m0 * K;
    const __half* Wb = W + (size_t)n0 * K;

#define LOAD_SLAB(it, buf)                                                      \
    {                                                                           \
        const int k0 = (it) << 6;                                               \
        __half* ad = As + (buf) * BM * LDA;                                     \
        __half* wd = Ws + (buf) * BN * LDA;                                     \
        _Pragma("unroll")                                                       \
        for (int i = 0; i < 4; i++) {                                           \
            int ch = tid + i * 256;          /* 0..1023 */                      \
            int r = ch >> 3, c8 = (ch & 7) << 3;                                \
            cp16(ad + r * LDA + c8, Ab + (size_t)r * K + k0 + c8);              \
            cp16(wd + r * LDA + c8, Wb + (size_t)r * K + k0 + c8);              \
        }                                                                       \
    }

    const int nIter = K >> 6;
    LOAD_SLAB(0, 0); CP_COMMIT();
    for (int it = 0; it < nIter; ++it) {
        const int buf = it & 1;
        if (it + 1 < nIter) { LOAD_SLAB(it + 1, buf ^ 1); CP_COMMIT(); CP_WAIT1(); }
        else CP_WAIT0();
        __syncthreads();
        const __half* as = As + buf * BM * LDA;
        const __half* ws = Ws + buf * BN * LDA;
#pragma unroll
        for (int kk = 0; kk < BKg; kk += 16) {
            wmma::fragment<wmma::matrix_a, 16, 16, 16, __half, wmma::row_major> a[4];
            wmma::fragment<wmma::matrix_b, 16, 16, 16, __half, wmma::col_major> b[2];
#pragma unroll
            for (int i = 0; i < 4; i++)
                wmma::load_matrix_sync(a[i], &as[(wm * 64 + i * 16) * LDA + kk], LDA);
#pragma unroll
            for (int j = 0; j < 2; j++)
                wmma::load_matrix_sync(b[j], &ws[(wn * 32 + j * 16) * LDA + kk], LDA);
#pragma unroll
            for (int i = 0; i < 4; i++)
#pragma unroll
                for (int j = 0; j < 2; j++)
                    wmma::mma_sync(acc[i][j], a[i], b[j], acc[i][j]);
        }
        __syncthreads();
    }
#undef LOAD_SLAB
#pragma unroll
    for (int i = 0; i < 4; i++)
#pragma unroll
        for (int j = 0; j < 2; j++)
            wmma::store_matrix_sync(&C[(size_t)(m0 + wm * 64 + i * 16) * N + n0 + wn * 32 + j * 16],
                                    acc[i][j], N, wmma::mem_row_major);
}

__global__ __launch_bounds__(256) void gemm_proj(
    const __half* __restrict__ A, const __half* __restrict__ W, float* __restrict__ C, int K) {
    gemm_core(A, W, C, Ecfg, K, blockIdx.y * BM, blockIdx.x * BN);
}

__global__ __launch_bounds__(256) void gemm_qkv(
    const __half* __restrict__ x,
    const __half* __restrict__ Wq, const __half* __restrict__ Wk, const __half* __restrict__ Wv,
    float* __restrict__ Cq, float* __restrict__ Ck, float* __restrict__ Cv, int K) {
    const int ng = blockIdx.x * BN;
    const __half* W; float* C; int N, n0;
    if (ng < 1024)      { W = Wq; C = Cq; N = 1024; n0 = ng; }
    else if (ng < 1280) { W = Wk; C = Ck; N = 256;  n0 = ng - 1024; }
    else                { W = Wv; C = Cv; N = 256;  n0 = ng - 1280; }
    gemm_core(x, W, C, N, K, blockIdx.y * BM, n0);
}

// ---------------- rope + rmsnorm for Q (fp16, pre-scaled 1/8) ----------------
__global__ void rope_rms_kernel(const float* __restrict__ raw,
                                const float* __restrict__ cosb,
                                const float* __restrict__ sinb,
                                __half* __restrict__ dst, int T) {
    const int warp = threadIdx.x >> 5, lane = threadIdx.x & 31;
    const int t = blockIdx.x * 8 + warp;
    const int h = blockIdx.y, b = blockIdx.z;
    const int NH = gridDim.y;
    const float* src = raw + (((size_t)b * T + t) * NH + h) * 64;
    float x1 = src[lane], x2 = src[32 + lane];
    float c = cosb[(size_t)t * 32 + lane];
    float s = sinb[(size_t)t * 32 + lane];
    float r1 = x1 * c + x2 * s;
    float r2 = x2 * c - x1 * s;
    float ss = r1 * r1 + r2 * r2;
#pragma unroll
    for (int o = 16; o; o >>= 1) ss += __shfl_xor_sync(0xffffffffu, ss, o);
    float inv = rsqrtf(ss * (1.f / 64.f) + 1.1920929e-07f) * 0.125f;
    __half* d = dst + (((size_t)b * NH + h) * T + t) * 64;
    d[lane] = __float2half(r1 * inv);
    d[32 + lane] = __float2half(r2 * inv);
}

// ---------------- fused K rope+rms AND V gate (fp16) ----------------
__global__ void kv_post_kernel(const float* __restrict__ kraw,
                               const float* __restrict__ vraw,
                               const float* __restrict__ x,
                               const float* __restrict__ ve,
                               const float* __restrict__ cosb,
                               const float* __restrict__ sinb,
                               const float* __restrict__ Wgate,
                               __half* __restrict__ k_t,
                               __half* __restrict__ v_t, int T) {
    const int warp = threadIdx.x >> 5, lane = threadIdx.x & 31;
    const int t = blockIdx.x * 8 + warp;
    const int h = blockIdx.y, b = blockIdx.z;
    const size_t tok = (size_t)b * T + t;
    {
        const float* src = kraw + (tok * HKV + h) * 64;
        float x1 = src[lane], x2 = src[32 + lane];
        float c = cosb[(size_t)t * 32 + lane];
        float s = sinb[(size_t)t * 32 + lane];
        float r1 = x1 * c + x2 * s;
        float r2 = x2 * c - x1 * s;
        float ss = r1 * r1 + r2 * r2;
#pragma unroll
        for (int o = 16; o; o >>= 1) ss += __shfl_xor_sync(0xffffffffu, ss, o);
        float inv = rsqrtf(ss * (1.f / 64.f) + 1.1920929e-07f);
        __half* d = k_t + (((size_t)b * HKV + h) * T + t) * 64;
        d[lane] = __float2half(r1 * inv);
        d[32 + lane] = __float2half(r2 * inv);
    }
    {
        float g = x[tok * Ecfg + lane] * Wgate[h * 32 + lane];
#pragma unroll
        for (int o = 16; o; o >>= 1) g += __shfl_xor_sync(0xffffffffu, g, o);
        float gate = 2.f / (1.f + __expf(-g));
        const float* vs = vraw + (tok * HKV + h) * 64;
        const float* ves = ve + (tok * HKV + h) * 64;
        __half* d = v_t + (((size_t)b * HKV + h) * T + t) * 64;
        d[lane] = __float2half(vs[lane] + gate * ves[lane]);
        d[32 + lane] = __float2half(vs[32 + lane] + gate * ves[32 + lane]);
    }
}

// ================ flash attention: raw mma + register softmax (R10 exact) ================
// 128 thr = 4 warps; warp owns rows [32w, 32w+32) of a 128-row Q tile.
__global__ __launch_bounds__(128) void attn_mma(
    const __half* __restrict__ q, const __half* __restrict__ k,
    const __half* __restrict__ v, __half* __restrict__ out,
    const int* __restrict__ wptr, int T) {
    extern __shared__ __half smh[];
    __half* Ks = smh;                  // 2 * 64 * LDK
    __half* Vs = smh + 2 * 64 * LDK;   // 2 * 64 * LDK
    const uint32_t ks0 = smem_u32(Ks);
    const uint32_t vs0 = smem_u32(Vs);

    const int qtile = blockIdx.x, h = blockIdx.y, b = blockIdx.z;
    const int W = wptr[0];
    const int tid = threadIdx.x;
    const int warp = tid >> 5, lane = tid & 31;
    const int qbase = qtile * 128;
    const int rq = lane >> 2;
    const int qc = (lane & 3) << 1;

    const int krow = ((lane >> 4) << 3) + (lane & 7);
    const int kcol = ((lane >> 3) & 1) << 3;
    const int vrow = (((lane >> 3) & 1) << 3) + (lane & 7);
    const int vcol = (lane >> 4) << 3;

    uint32_t qa[2][4][4];
#pragma unroll
    for (int i = 0; i < 2; i++) {
        const __half* q0 = q + ((size_t)(b * Hh + h) * T + qbase + warp * 32 + i * 16 + rq) * Dd;
        const __half* q8 = q0 + 8 * Dd;
#pragma unroll
        for (int t = 0; t < 4; t++) {
            qa[i][t][0] = *reinterpret_cast<const uint32_t*>(q0 + t * 16 + qc);
            qa[i][t][1] = *reinterpret_cast<const uint32_t*>(q8 + t * 16 + qc);
            qa[i][t][2] = *reinterpret_cast<const uint32_t*>(q0 + t * 16 + 8 + qc);
            qa[i][t][3] = *reinterpret_cast<const uint32_t*>(q8 + t * 16 + 8 + qc);
        }
    }

    float o[2][8][4];
#pragma unroll
    for (int i = 0; i < 2; i++)
#pragma unroll
        for (int j = 0; j < 8; j++)
#pragma unroll
            for (int c = 0; c < 4; c++) o[i][j][c] = 0.f;
    float lsum[2][2] = {{0.f, 0.f}, {0.f, 0.f}};

    const int hkv = h >> 2;
    const __half* kb = k + (size_t)(b * HKV + hkv) * T * Dd;
    const __half* vb = v + (size_t)(b * HKV + hkv) * T * Dd;
    int kmin = qbase - W; if (kmin < 0) kmin = 0;
    const int t0 = kmin >> 6;
    const int ktend = 2 * qtile + 1;

#define LOAD_KV(kt, buf)                                                        \
    {                                                                           \
        const __half* kp = kb + (size_t)(kt) * 64 * Dd;                         \
        const __half* vp = vb + (size_t)(kt) * 64 * Dd;                         \
        __half* kd = Ks + (buf) * 64 * LDK;                                     \
        __half* vd = Vs + (buf) * 64 * LDK;                                     \
        _Pragma("unroll")                                                       \
        for (int i = 0; i < 4; i++) {                                           \
            int ch = tid + i * 128;                                             \
            int r = ch >> 3, c8 = (ch & 7) << 3;                                \
            cp16(kd + r * LDK + c8, kp + r * 64 + c8);                          \
            cp16(vd + r * LDK + c8, vp + r * 64 + c8);                          \
        }                                                                       \
    }

    LOAD_KV(t0, 0); CP_COMMIT();

    for (int kt = t0; kt <= ktend; ++kt) {
        const int buf = (kt - t0) & 1;
        if (kt < ktend) { LOAD_KV(kt + 1, buf ^ 1); CP_COMMIT(); CP_WAIT1(); }
        else CP_WAIT0();
        __syncthreads();
        const uint32_t ksb = ks0 + buf * 64 * LDK * 2;
        const uint32_t vsb = vs0 + buf * 64 * LDK * 2;

#pragma unroll
        for (int t = 0; t < 4; t++) {
            float s[2][2][4];
#pragma unroll
            for (int i = 0; i < 2; i++)
#pragma unroll
                for (int jj = 0; jj < 2; jj++)
#pragma unroll
                    for (int c = 0; c < 4; c++) s[i][jj][c] = 0.f;
#pragma unroll
            for (int kd = 0; kd < 4; kd++) {
                uint32_t kbf[4];
                ldm4(kbf, ksb + (uint32_t)(((t * 16 + krow) * LDK + kd * 16 + kcol) * 2));
                mma16816(s[0][0], qa[0][kd], kbf[0], kbf[1]);
                mma16816(s[0][1], qa[0][kd], kbf[2], kbf[3]);
                mma16816(s[1][0], qa[1][kd], kbf[0], kbf[1]);
                mma16816(s[1][1], qa[1][kd], kbf[2], kbf[3]);
            }
            uint32_t pa[2][4];
#pragma unroll
            for (int i = 0; i < 2; i++) {
                const int row0 = qbase + warp * 32 + i * 16 + rq;
#pragma unroll
                for (int jj = 0; jj < 2; jj++) {
                    const int colb = (kt << 6) + t * 16 + jj * 8 + qc;
#pragma unroll
                    for (int c = 0; c < 4; c++) {
                        const int row = row0 + ((c >> 1) << 3);
                        const int col = colb + (c & 1);
                        float pv = 0.f;
                        if (col <= row && col >= row - W) {
                            pv = fast_exp2(fmaf(s[i][jj][c], LOG2E_F, NBIAS_F));
                            lsum[i][c >> 1] += pv;
                        }
                        s[i][jj][c] = pv;
                    }
                    __half2 lo = __floats2half2_rn(s[i][jj][0], s[i][jj][1]);
                    __half2 hi = __floats2half2_rn(s[i][jj][2], s[i][jj][3]);
                    pa[i][jj * 2 + 0] = *reinterpret_cast<uint32_t*>(&lo);
                    pa[i][jj * 2 + 1] = *reinterpret_cast<uint32_t*>(&hi);
                }
            }
#pragma unroll
            for (int jdp = 0; jdp < 4; jdp++) {
                uint32_t vbf[4];
                ldm4t(vbf, vsb + (uint32_t)(((t * 16 + vrow) * LDK + jdp * 16 + vcol) * 2));
                mma16816(o[0][jdp * 2 + 0], pa[0], vbf[0], vbf[1]);
                mma16816(o[0][jdp * 2 + 1], pa[0], vbf[2], vbf[3]);
                mma16816(o[1][jdp * 2 + 0], pa[1], vbf[0], vbf[1]);
                mma16816(o[1][jdp * 2 + 1], pa[1], vbf[2], vbf[3]);
            }
        }
        __syncthreads();
    }
#undef LOAD_KV

#pragma unroll
    for (int i = 0; i < 2; i++) {
#pragma unroll
        for (int rh = 0; rh < 2; rh++) {
            float l = lsum[i][rh];
            l += __shfl_xor_sync(0xffffffffu, l, 1);
            l += __shfl_xor_sync(0xffffffffu, l, 2);
            const float inv = 1.f / l;
            const int qrow = qbase + warp * 32 + i * 16 + rq + rh * 8;
            __half* op = out + ((size_t)(b * T + qrow) * Hh + h) * Dd + qc;
#pragma unroll
            for (int jd = 0; jd < 8; jd++) {
                __half2 hv = __floats2half2_rn(o[i][jd][rh * 2] * inv,
                                               o[i][jd][rh * 2 + 1] * inv);
                *reinterpret_cast<__half2*>(op + jd * 8) = hv;
            }
        }
    }
}

// ---------------- launch ----------------
extern "C" void kernel_launch(void* const* d_in, const int* in_sizes, int n_in,
                              void* d_out, int out_size) {
    const float* x     = (const float*)d_in[0];
    const float* ve    = (const float*)d_in[1];
    const float* cosb  = (const float*)d_in[2];
    const float* sinb  = (const float*)d_in[3];
    const float* Wq    = (const float*)d_in[4];
    const float* Wk    = (const float*)d_in[5];
    const float* Wv    = (const float*)d_in[6];
    const float* Wproj = (const float*)d_in[7];
    const float* Wgate = (const float*)d_in[8];
    const int*   wsz   = (const int*)d_in[9];

    int T = in_sizes[2] / 32;
    int B = in_sizes[0] / (T * Ecfg);
    int M = B * T;

    float *qraw, *kraw, *vraw;
    __half *qt, *kt, *vt, *y, *xh, *wqh, *wkh, *wvh, *wph;
    cudaGetSymbolAddress((void**)&qraw, g_qraw);
    cudaGetSymbolAddress((void**)&kraw, g_kraw);
    cudaGetSymbolAddress((void**)&vraw, g_vraw);
    cudaGetSymbolAddress((void**)&qt,   g_qt);
    cudaGetSymbolAddress((void**)&kt,   g_kt);
    cudaGetSymbolAddress((void**)&vt,   g_vt);
    cudaGetSymbolAddress((void**)&y,    g_y);
    cudaGetSymbolAddress((void**)&xh,   g_xh);
    cudaGetSymbolAddress((void**)&wqh,  g_wqh);
    cudaGetSymbolAddress((void**)&wkh,  g_wkh);
    cudaGetSymbolAddress((void**)&wvh,  g_wvh);
    cudaGetSymbolAddress((void**)&wph,  g_wph);

    const int gemm_smem = 2 * (BM + BN) * LDA * 2;   // 73728
    const int attn_smem = 4 * 64 * LDK * 2;          // 36864
    cudaFuncSetAttribute(gemm_qkv,  cudaFuncAttributeMaxDynamicSharedMemorySize, gemm_smem);
    cudaFuncSetAttribute(gemm_proj, cudaFuncAttributeMaxDynamicSharedMemorySize, gemm_smem);
    cudaFuncSetAttribute(attn_mma,  cudaFuncAttributeMaxDynamicSharedMemorySize, attn_smem);

    {
        int n4x = M * Ecfg / 4;
        int total = n4x + N4_WQ + N4_WK + N4_WV + N4_WP;
        cvt_all<<<(total + 255) / 256, 256>>>(x, Wq, Wk, Wv, Wproj,
                                              xh, wqh, wkh, wvh, wph, n4x);
    }

    gemm_qkv<<<dim3(1536 / BN, M / BM), 256, gemm_smem>>>(xh, wqh, wkh, wvh, qraw, kraw, vraw, Ecfg);

    rope_rms_kernel<<<dim3(T / 8, Hh, B), 256>>>(qraw, cosb, sinb, qt, T);
    kv_post_kernel <<<dim3(T / 8, HKV, B), 256>>>(kraw, vraw, x, ve, cosb, sinb, Wgate, kt, vt, T);

    attn_mma<<<dim3(T / 128, Hh, B), 128, attn_smem>>>(qt, kt, vt, y, wsz, T);

    gemm_proj<<<dim3(Ecfg / BN, M / BM), 256, gemm_smem>>>(y, wph, (float*)d_out, Ecfg);
}

// round 13
// speedup vs baseline: 1.2531x; 1.0080x over previous
#include <cuda_runtime.h>
#include <cuda_fp16.h>
#include <mma.h>
#include <cstdint>

using namespace nvcuda;

#define Ecfg 1024
#define Hh   16
#define HKV  4
#define Dd   64

#define BM  128
#define BN  128
#define BKg 64
#define LDA 72    // halves (64 + 8 pad)
#define LDK 72    // halves
#define NSTG 3    // cp.async pipeline stages (GEMM)

// ---------------- scratch (device globals) ----------------
__device__ float  g_qraw[2 * 2048 * 1024];
__device__ float  g_kraw[2 * 2048 * 256];
__device__ float  g_vraw[2 * 2048 * 256];
__device__ __half g_qt [2 * 16 * 2048 * 64];
__device__ __half g_kt [2 * 4  * 2048 * 64];
__device__ __half g_vt [2 * 4  * 2048 * 64];
__device__ __half g_y  [2 * 2048 * 1024];
__device__ __half g_xh [2 * 2048 * 1024];
__device__ __half g_wqh[1024 * 1024];
__device__ __half g_wkh[256 * 1024];
__device__ __half g_wvh[256 * 1024];
__device__ __half g_wph[1024 * 1024];

// ---------------- cp.async helpers ----------------
__device__ __forceinline__ void cp16(void* smem_dst, const void* gsrc) {
    uint32_t s = (uint32_t)__cvta_generic_to_shared(smem_dst);
    asm volatile("cp.async.cg.shared.global [%0], [%1], 16;\n" :: "r"(s), "l"(gsrc));
}
#define CP_COMMIT() asm volatile("cp.async.commit_group;\n" ::: "memory")
#define CP_WAIT1()  asm volatile("cp.async.wait_group 1;\n" ::: "memory")
#define CP_WAIT0()  asm volatile("cp.async.wait_group 0;\n" ::: "memory")

__device__ __forceinline__ uint32_t smem_u32(const void* p) {
    return (uint32_t)__cvta_generic_to_shared(p);
}

// ---------------- mma / ldmatrix primitives ----------------
__device__ __forceinline__ void mma16816(float d[4], const uint32_t a[4],
                                         uint32_t b0, uint32_t b1) {
    asm volatile(
        "mma.sync.aligned.m16n8k16.row.col.f32.f16.f16.f32 "
        "{%0,%1,%2,%3}, {%4,%5,%6,%7}, {%8,%9}, {%0,%1,%2,%3};"
        : "+f"(d[0]), "+f"(d[1]), "+f"(d[2]), "+f"(d[3])
        : "r"(a[0]), "r"(a[1]), "r"(a[2]), "r"(a[3]), "r"(b0), "r"(b1));
}
__device__ __forceinline__ void ldm4(uint32_t r[4], uint32_t addr) {
    asm volatile("ldmatrix.sync.aligned.m8n8.x4.shared.b16 {%0,%1,%2,%3}, [%4];"
                 : "=r"(r[0]), "=r"(r[1]), "=r"(r[2]), "=r"(r[3]) : "r"(addr));
}
__device__ __forceinline__ void ldm4t(uint32_t r[4], uint32_t addr) {
    asm volatile("ldmatrix.sync.aligned.m8n8.x4.trans.shared.b16 {%0,%1,%2,%3}, [%4];"
                 : "=r"(r[0]), "=r"(r[1]), "=r"(r[2]), "=r"(r[3]) : "r"(addr));
}

// ---------------- fast exp2 (no MUFU) ----------------
__device__ __forceinline__ float fast_exp2(float x) {
    float t = x + 12582912.0f;
    int   ei = __float_as_int(t) - 0x4B400000;
    float f = x - (t - 12582912.0f);
    float e = fmaf(f, 0.0013333558f, 0.0096181291f);
    e = fmaf(f, e, 0.0555041087f);
    e = fmaf(f, e, 0.2402265070f);
    e = fmaf(f, e, 0.6931471806f);
    e = fmaf(f, e, 1.0f);
    return __int_as_float(__float_as_int(e) + (ei << 23));
}
#define LOG2E_F  1.4426950408889634f
#define NBIAS_F  (-11.541560327111707f)

// ---------------- fused fp16 convert of x + all weights (1 launch) ----------------
#define N4_WQ 262144
#define N4_WK 65536
#define N4_WV 65536
#define N4_WP 262144
__global__ void cvt_all(const float* __restrict__ x,  const float* __restrict__ wq,
                        const float* __restrict__ wk, const float* __restrict__ wv,
                        const float* __restrict__ wp,
                        __half* __restrict__ xo, __half* __restrict__ wqo,
                        __half* __restrict__ wko, __half* __restrict__ wvo,
                        __half* __restrict__ wpo, int n4x) {
    int i = blockIdx.x * blockDim.x + threadIdx.x;
    const float4* s; __half* d; int j;
    if (i < n4x) { s = (const float4*)x; d = xo; j = i; }
    else {
        i -= n4x;
        if (i < N4_WQ)                          { s = (const float4*)wq; d = wqo; j = i; }
        else if (i < N4_WQ + N4_WK)             { s = (const float4*)wk; d = wko; j = i - N4_WQ; }
        else if (i < N4_WQ + N4_WK + N4_WV)     { s = (const float4*)wv; d = wvo; j = i - N4_WQ - N4_WK; }
        else if (i < N4_WQ + N4_WK + N4_WV + N4_WP) { s = (const float4*)wp; d = wpo; j = i - N4_WQ - N4_WK - N4_WV; }
        else return;
    }
    float4 v = s[j];
    __half2 h0 = __floats2half2_rn(v.x, v.y);
    __half2 h1 = __floats2half2_rn(v.z, v.w);
    *reinterpret_cast<__half2*>(&d[j * 4])     = h0;
    *reinterpret_cast<__half2*>(&d[j * 4 + 2]) = h1;
}

// ================= FP16 GEMM, cp.async 3-stage, BK=64 =================
// BM=BN=128, 256 thr = 8 warps (2M x 4N), warp tile 64x32.
// 3-stage ring: ONE __syncthreads per K-slab (write target == buffer read 2 iters ago).
__device__ __forceinline__ void gemm_core(
    const __half* __restrict__ A, const __half* __restrict__ W,
    float* __restrict__ C, int N, int K, int m0, int n0) {
    extern __shared__ __half smh[];
    __half* As = smh;                          // NSTG * 128 * LDA
    __half* Ws = smh + NSTG * BM * LDA;        // NSTG * 128 * LDA
    const int tid = threadIdx.x;
    const int warp = tid >> 5;
    const int wm = warp >> 2;
    const int wn = warp & 3;

    wmma::fragment<wmma::accumulator, 16, 16, 16, float> acc[4][2];
#pragma unroll
    for (int i = 0; i < 4; i++)
#pragma unroll
        for (int j = 0; j < 2; j++) wmma::fill_fragment(acc[i][j], 0.f);

    const __half* Ab = A + (size_t)m0 * K;
    const __half* Wb = W + (size_t)n0 * K;

#define LOAD_SLAB(it, buf)                                                      \
    {                                                                           \
        const int k0 = (it) << 6;                                               \
        __half* ad = As + (buf) * BM * LDA;                                     \
        __half* wd = Ws + (buf) * BN * LDA;                                     \
        _Pragma("unroll")                                                       \
        for (int i = 0; i < 4; i++) {                                           \
            int ch = tid + i * 256;          /* 0..1023 */                      \
            int r = ch >> 3, c8 = (ch & 7) << 3;                                \
            cp16(ad + r * LDA + c8, Ab + (size_t)r * K + k0 + c8);              \
            cp16(wd + r * LDA + c8, Wb + (size_t)r * K + k0 + c8);              \
        }                                                                       \
    }

    const int nIter = K >> 6;                  // 16 for K=1024
    LOAD_SLAB(0, 0); CP_COMMIT();
    LOAD_SLAB(1, 1); CP_COMMIT();

    int buf = 0;
    for (int it = 0; it < nIter; ++it) {
        if (it + 1 < nIter) CP_WAIT1(); else CP_WAIT0();
        __syncthreads();
        // prefetch slab it+2 into the buffer read at iteration it-1 (all warps past sync)
        if (it + 2 < nIter) {
            int nb = buf + 2; if (nb >= NSTG) nb -= NSTG;
            LOAD_SLAB(it + 2, nb); CP_COMMIT();
        }
        const __half* as = As + buf * BM * LDA;
        const __half* ws = Ws + buf * BN * LDA;
#pragma unroll
        for (int kk = 0; kk < BKg; kk += 16) {
            wmma::fragment<wmma::matrix_a, 16, 16, 16, __half, wmma::row_major> a[4];
            wmma::fragment<wmma::matrix_b, 16, 16, 16, __half, wmma::col_major> b[2];
#pragma unroll
            for (int i = 0; i < 4; i++)
                wmma::load_matrix_sync(a[i], &as[(wm * 64 + i * 16) * LDA + kk], LDA);
#pragma unroll
            for (int j = 0; j < 2; j++)
                wmma::load_matrix_sync(b[j], &ws[(wn * 32 + j * 16) * LDA + kk], LDA);
#pragma unroll
            for (int i = 0; i < 4; i++)
#pragma unroll
                for (int j = 0; j < 2; j++)
                    wmma::mma_sync(acc[i][j], a[i], b[j], acc[i][j]);
        }
        if (++buf == NSTG) buf = 0;
    }
#undef LOAD_SLAB
    __syncthreads();
#pragma unroll
    for (int i = 0; i < 4; i++)
#pragma unroll
        for (int j = 0; j < 2; j++)
            wmma::store_matrix_sync(&C[(size_t)(m0 + wm * 64 + i * 16) * N + n0 + wn * 32 + j * 16],
                                    acc[i][j], N, wmma::mem_row_major);
}

__global__ __launch_bounds__(256) void gemm_proj(
    const __half* __restrict__ A, const __half* __restrict__ W, float* __restrict__ C, int K) {
    gemm_core(A, W, C, Ecfg, K, blockIdx.y * BM, blockIdx.x * BN);
}

__global__ __launch_bounds__(256) void gemm_qkv(
    const __half* __restrict__ x,
    const __half* __restrict__ Wq, const __half* __restrict__ Wk, const __half* __restrict__ Wv,
    float* __restrict__ Cq, float* __restrict__ Ck, float* __restrict__ Cv, int K) {
    const int ng = blockIdx.x * BN;
    const __half* W; float* C; int N, n0;
    if (ng < 1024)      { W = Wq; C = Cq; N = 1024; n0 = ng; }
    else if (ng < 1280) { W = Wk; C = Ck; N = 256;  n0 = ng - 1024; }
    else                { W = Wv; C = Cv; N = 256;  n0 = ng - 1280; }
    gemm_core(x, W, C, N, K, blockIdx.y * BM, n0);
}

// ---------------- rope + rmsnorm for Q (fp16, pre-scaled 1/8) ----------------
__global__ void rope_rms_kernel(const float* __restrict__ raw,
                                const float* __restrict__ cosb,
                                const float* __restrict__ sinb,
                                __half* __restrict__ dst, int T) {
    const int warp = threadIdx.x >> 5, lane = threadIdx.x & 31;
    const int t = blockIdx.x * 8 + warp;
    const int h = blockIdx.y, b = blockIdx.z;
    const int NH = gridDim.y;
    const float* src = raw + (((size_t)b * T + t) * NH + h) * 64;
    float x1 = src[lane], x2 = src[32 + lane];
    float c = cosb[(size_t)t * 32 + lane];
    float s = sinb[(size_t)t * 32 + lane];
    float r1 = x1 * c + x2 * s;
    float r2 = x2 * c - x1 * s;
    float ss = r1 * r1 + r2 * r2;
#pragma unroll
    for (int o = 16; o; o >>= 1) ss += __shfl_xor_sync(0xffffffffu, ss, o);
    float inv = rsqrtf(ss * (1.f / 64.f) + 1.1920929e-07f) * 0.125f;
    __half* d = dst + (((size_t)b * NH + h) * T + t) * 64;
    d[lane] = __float2half(r1 * inv);
    d[32 + lane] = __float2half(r2 * inv);
}

// ---------------- fused K rope+rms AND V gate (fp16) ----------------
__global__ void kv_post_kernel(const float* __restrict__ kraw,
                               const float* __restrict__ vraw,
                               const float* __restrict__ x,
                               const float* __restrict__ ve,
                               const float* __restrict__ cosb,
                               const float* __restrict__ sinb,
                               const float* __restrict__ Wgate,
                               __half* __restrict__ k_t,
                               __half* __restrict__ v_t, int T) {
    const int warp = threadIdx.x >> 5, lane = threadIdx.x & 31;
    const int t = blockIdx.x * 8 + warp;
    const int h = blockIdx.y, b = blockIdx.z;
    const size_t tok = (size_t)b * T + t;
    {
        const float* src = kraw + (tok * HKV + h) * 64;
        float x1 = src[lane], x2 = src[32 + lane];
        float c = cosb[(size_t)t * 32 + lane];
        float s = sinb[(size_t)t * 32 + lane];
        float r1 = x1 * c + x2 * s;
        float r2 = x2 * c - x1 * s;
        float ss = r1 * r1 + r2 * r2;
#pragma unroll
        for (int o = 16; o; o >>= 1) ss += __shfl_xor_sync(0xffffffffu, ss, o);
        float inv = rsqrtf(ss * (1.f / 64.f) + 1.1920929e-07f);
        __half* d = k_t + (((size_t)b * HKV + h) * T + t) * 64;
        d[lane] = __float2half(r1 * inv);
        d[32 + lane] = __float2half(r2 * inv);
    }
    {
        float g = x[tok * Ecfg + lane] * Wgate[h * 32 + lane];
#pragma unroll
        for (int o = 16; o; o >>= 1) g += __shfl_xor_sync(0xffffffffu, g, o);
        float gate = 2.f / (1.f + __expf(-g));
        const float* vs = vraw + (tok * HKV + h) * 64;
        const float* ves = ve + (tok * HKV + h) * 64;
        __half* d = v_t + (((size_t)b * HKV + h) * T + t) * 64;
        d[lane] = __float2half(vs[lane] + gate * ves[lane]);
        d[32 + lane] = __float2half(vs[32 + lane] + gate * ves[32 + lane]);
    }
}

// ================ flash attention: raw mma + register softmax (R10/R12 exact) ================
__global__ __launch_bounds__(128) void attn_mma(
    const __half* __restrict__ q, const __half* __restrict__ k,
    const __half* __restrict__ v, __half* __restrict__ out,
    const int* __restrict__ wptr, int T) {
    extern __shared__ __half smh[];
    __half* Ks = smh;                  // 2 * 64 * LDK
    __half* Vs = smh + 2 * 64 * LDK;   // 2 * 64 * LDK
    const uint32_t ks0 = smem_u32(Ks);
    const uint32_t vs0 = smem_u32(Vs);

    const int qtile = blockIdx.x, h = blockIdx.y, b = blockIdx.z;
    const int W = wptr[0];
    const int tid = threadIdx.x;
    const int warp = tid >> 5, lane = tid & 31;
    const int qbase = qtile * 128;
    const int rq = lane >> 2;
    const int qc = (lane & 3) << 1;

    const int krow = ((lane >> 4) << 3) + (lane & 7);
    const int kcol = ((lane >> 3) & 1) << 3;
    const int vrow = (((lane >> 3) & 1) << 3) + (lane & 7);
    const int vcol = (lane >> 4) << 3;

    uint32_t qa[2][4][4];
#pragma unroll
    for (int i = 0; i < 2; i++) {
        const __half* q0 = q + ((size_t)(b * Hh + h) * T + qbase + warp * 32 + i * 16 + rq) * Dd;
        const __half* q8 = q0 + 8 * Dd;
#pragma unroll
        for (int t = 0; t < 4; t++) {
            qa[i][t][0] = *reinterpret_cast<const uint32_t*>(q0 + t * 16 + qc);
            qa[i][t][1] = *reinterpret_cast<const uint32_t*>(q8 + t * 16 + qc);
            qa[i][t][2] = *reinterpret_cast<const uint32_t*>(q0 + t * 16 + 8 + qc);
            qa[i][t][3] = *reinterpret_cast<const uint32_t*>(q8 + t * 16 + 8 + qc);
        }
    }

    float o[2][8][4];
#pragma unroll
    for (int i = 0; i < 2; i++)
#pragma unroll
        for (int j = 0; j < 8; j++)
#pragma unroll
            for (int c = 0; c < 4; c++) o[i][j][c] = 0.f;
    float lsum[2][2] = {{0.f, 0.f}, {0.f, 0.f}};

    const int hkv = h >> 2;
    const __half* kb = k + (size_t)(b * HKV + hkv) * T * Dd;
    const __half* vb = v + (size_t)(b * HKV + hkv) * T * Dd;
    int kmin = qbase - W; if (kmin < 0) kmin = 0;
    const int t0 = kmin >> 6;
    const int ktend = 2 * qtile + 1;

#define LOAD_KV(kt, buf)                                                        \
    {                                                                           \
        const __half* kp = kb + (size_t)(kt) * 64 * Dd;                         \
        const __half* vp = vb + (size_t)(kt) * 64 * Dd;                         \
        __half* kd = Ks + (buf) * 64 * LDK;                                     \
        __half* vd = Vs + (buf) * 64 * LDK;                                     \
        _Pragma("unroll")                                                       \
        for (int i = 0; i < 4; i++) {                                           \
            int ch = tid + i * 128;                                             \
            int r = ch >> 3, c8 = (ch & 7) << 3;                                \
            cp16(kd + r * LDK + c8, kp + r * 64 + c8);                          \
            cp16(vd + r * LDK + c8, vp + r * 64 + c8);                          \
        }                                                                       \
    }

    LOAD_KV(t0, 0); CP_COMMIT();

    for (int kt = t0; kt <= ktend; ++kt) {
        const int buf = (kt - t0) & 1;
        if (kt < ktend) { LOAD_KV(kt + 1, buf ^ 1); CP_COMMIT(); CP_WAIT1(); }
        else CP_WAIT0();
        __syncthreads();
        const uint32_t ksb = ks0 + buf * 64 * LDK * 2;
        const uint32_t vsb = vs0 + buf * 64 * LDK * 2;

#pragma unroll
        for (int t = 0; t < 4; t++) {
            float s[2][2][4];
#pragma unroll
            for (int i = 0; i < 2; i++)
#pragma unroll
                for (int jj = 0; jj < 2; jj++)
#pragma unroll
                    for (int c = 0; c < 4; c++) s[i][jj][c] = 0.f;
#pragma unroll
            for (int kd = 0; kd < 4; kd++) {
                uint32_t kbf[4];
                ldm4(kbf, ksb + (uint32_t)(((t * 16 + krow) * LDK + kd * 16 + kcol) * 2));
                mma16816(s[0][0], qa[0][kd], kbf[0], kbf[1]);
                mma16816(s[0][1], qa[0][kd], kbf[2], kbf[3]);
                mma16816(s[1][0], qa[1][kd], kbf[0], kbf[1]);
                mma16816(s[1][1], qa[1][kd], kbf[2], kbf[3]);
            }
            uint32_t pa[2][4];
#pragma unroll
            for (int i = 0; i < 2; i++) {
                const int row0 = qbase + warp * 32 + i * 16 + rq;
#pragma unroll
                for (int jj = 0; jj < 2; jj++) {
                    const int colb = (kt << 6) + t * 16 + jj * 8 + qc;
#pragma unroll
                    for (int c = 0; c < 4; c++) {
                        const int row = row0 + ((c >> 1) << 3);
                        const int col = colb + (c & 1);
                        float pv = 0.f;
                        if (col <= row && col >= row - W) {
                            pv = fast_exp2(fmaf(s[i][jj][c], LOG2E_F, NBIAS_F));
                            lsum[i][c >> 1] += pv;
                        }
                        s[i][jj][c] = pv;
                    }
                    __half2 lo = __floats2half2_rn(s[i][jj][0], s[i][jj][1]);
                    __half2 hi = __floats2half2_rn(s[i][jj][2], s[i][jj][3]);
                    pa[i][jj * 2 + 0] = *reinterpret_cast<uint32_t*>(&lo);
                    pa[i][jj * 2 + 1] = *reinterpret_cast<uint32_t*>(&hi);
                }
            }
#pragma unroll
            for (int jdp = 0; jdp < 4; jdp++) {
                uint32_t vbf[4];
                ldm4t(vbf, vsb + (uint32_t)(((t * 16 + vrow) * LDK + jdp * 16 + vcol) * 2));
                mma16816(o[0][jdp * 2 + 0], pa[0], vbf[0], vbf[1]);
                mma16816(o[0][jdp * 2 + 1], pa[0], vbf[2], vbf[3]);
                mma16816(o[1][jdp * 2 + 0], pa[1], vbf[0], vbf[1]);
                mma16816(o[1][jdp * 2 + 1], pa[1], vbf[2], vbf[3]);
            }
        }
        __syncthreads();
    }
#undef LOAD_KV

#pragma unroll
    for (int i = 0; i < 2; i++) {
#pragma unroll
        for (int rh = 0; rh < 2; rh++) {
            float l = lsum[i][rh];
            l += __shfl_xor_sync(0xffffffffu, l, 1);
            l += __shfl_xor_sync(0xffffffffu, l, 2);
            const float inv = 1.f / l;
            const int qrow = qbase + warp * 32 + i * 16 + rq + rh * 8;
            __half* op = out + ((size_t)(b * T + qrow) * Hh + h) * Dd + qc;
#pragma unroll
            for (int jd = 0; jd < 8; jd++) {
                __half2 hv = __floats2half2_rn(o[i][jd][rh * 2] * inv,
                                               o[i][jd][rh * 2 + 1] * inv);
                *reinterpret_cast<__half2*>(op + jd * 8) = hv;
            }
        }
    }
}

// ---------------- launch ----------------
extern "C" void kernel_launch(void* const* d_in, const int* in_sizes, int n_in,
                              void* d_out, int out_size) {
    const float* x     = (const float*)d_in[0];
    const float* ve    = (const float*)d_in[1];
    const float* cosb  = (const float*)d_in[2];
    const float* sinb  = (const float*)d_in[3];
    const float* Wq    = (const float*)d_in[4];
    const float* Wk    = (const float*)d_in[5];
    const float* Wv    = (const float*)d_in[6];
    const float* Wproj = (const float*)d_in[7];
    const float* Wgate = (const float*)d_in[8];
    const int*   wsz   = (const int*)d_in[9];

    int T = in_sizes[2] / 32;
    int B = in_sizes[0] / (T * Ecfg);
    int M = B * T;

    float *qraw, *kraw, *vraw;
    __half *qt, *kt, *vt, *y, *xh, *wqh, *wkh, *wvh, *wph;
    cudaGetSymbolAddress((void**)&qraw, g_qraw);
    cudaGetSymbolAddress((void**)&kraw, g_kraw);
    cudaGetSymbolAddress((void**)&vraw, g_vraw);
    cudaGetSymbolAddress((void**)&qt,   g_qt);
    cudaGetSymbolAddress((void**)&kt,   g_kt);
    cudaGetSymbolAddress((void**)&vt,   g_vt);
    cudaGetSymbolAddress((void**)&y,    g_y);
    cudaGetSymbolAddress((void**)&xh,   g_xh);
    cudaGetSymbolAddress((void**)&wqh,  g_wqh);
    cudaGetSymbolAddress((void**)&wkh,  g_wkh);
    cudaGetSymbolAddress((void**)&wvh,  g_wvh);
    cudaGetSymbolAddress((void**)&wph,  g_wph);

    const int gemm_smem = NSTG * (BM + BN) * LDA * 2;   // 110592
    const int attn_smem = 4 * 64 * LDK * 2;             // 36864
    cudaFuncSetAttribute(gemm_qkv,  cudaFuncAttributeMaxDynamicSharedMemorySize, gemm_smem);
    cudaFuncSetAttribute(gemm_proj, cudaFuncAttributeMaxDynamicSharedMemorySize, gemm_smem);
    cudaFuncSetAttribute(attn_mma,  cudaFuncAttributeMaxDynamicSharedMemorySize, attn_smem);

    {
        int n4x = M * Ecfg / 4;
        int total = n4x + N4_WQ + N4_WK + N4_WV + N4_WP;
        cvt_all<<<(total + 255) / 256, 256>>>(x, Wq, Wk, Wv, Wproj,
                                              xh, wqh, wkh, wvh, wph, n4x);
    }

    gemm_qkv<<<dim3(1536 / BN, M / BM), 256, gemm_smem>>>(xh, wqh, wkh, wvh, qraw, kraw, vraw, Ecfg);

    rope_rms_kernel<<<dim3(T / 8, Hh, B), 256>>>(qraw, cosb, sinb, qt, T);
    kv_post_kernel <<<dim3(T / 8, HKV, B), 256>>>(kraw, vraw, x, ve, cosb, sinb, Wgate, kt, vt, T);

    attn_mma<<<dim3(T / 128, Hh, B), 128, attn_smem>>>(qt, kt, vt, y, wsz, T);

    gemm_proj<<<dim3(Ecfg / BN, M / BM), 256, gemm_smem>>>(y, wph, (float*)d_out, Ecfg);
}